// round 7
// baseline (speedup 1.0000x reference)
#include <cuda_runtime.h>
#include <math.h>

#define MAXN 50000
#define EPS  1e-8f
#define NPW  8
#define EPT  256            // edges per task

typedef unsigned long long ull;

// ---- scratch ----
__device__ float4 g_acc[MAXN * 3];     // [0..8]=frame sum, [9]=count
__device__ float  g_s  [MAXN * 128];   // pre-activation scalar out (K=144 partial)
__device__ float  g_vh [MAXN * 48];    // vh per node (layout [j*48 + d*16 + h] chunks)
__device__ float  g_vdf[MAXN * 12];    // vdf per node [c*4 + i]
__device__ int    g_ticket, g_ticket2, g_edge_done, g_main_done;

// ---- packed f32x2 helpers ----
__device__ __forceinline__ ull pk2(float lo, float hi) {
    ull r; asm("mov.b64 %0, {%1,%2};" : "=l"(r) : "f"(lo), "f"(hi)); return r;
}
__device__ __forceinline__ void unpk2(ull v, float& lo, float& hi) {
    asm("mov.b64 {%0,%1}, %2;" : "=f"(lo), "=f"(hi) : "l"(v));
}
__device__ __forceinline__ ull ffma2(ull a, ull b, ull c) {
    ull d; asm("fma.rn.f32x2 %0, %1, %2, %3;" : "=l"(d) : "l"(a), "l"(b), "l"(c));
    return d;
}
__device__ __forceinline__ int ld_acq(const int* p) {
    int v; asm volatile("ld.acquire.gpu.b32 %0, [%1];" : "=r"(v) : "l"(p)); return v;
}

// ---- shared layout (floats) ----
#define OFF_WSO    0                        // [k*132 + o], k<153
#define SZ_WSO     20200
#define OFF_WG     (OFF_WSO + SZ_WSO)       // [o*134 + k]
#define SZ_WG      2144
#define OFF_WUP    (OFF_WG + SZ_WG)         // [h*16 + o]
#define SZ_WUP     256
#define OFF_WDOWN  (OFF_WUP + SZ_WUP)       // [c*16 + h]
#define SZ_WDOWN   256
#define OFF_WDF    (OFF_WDOWN + SZ_WDOWN)   // [k*3 + c]
#define SZ_WDF     48
#define OFF_BSO    (OFF_WDF + SZ_WDF)
#define SZ_BSO     128
#define OFF_BG     (OFF_BSO + SZ_BSO)
#define SZ_BG      16
#define OFF_WARP   (OFF_BG + SZ_BG)         // even -> 8B aligned per-warp base
// per-warp wb (1920 floats):
//  main: mgT[k*10+j] k<144 (1440; rows 0..38 transiently = vec buffer), vhb @1536 (384)
//  fix:  msil[j*132+k] (1056), mgT9 @1088 ([q*10+j], 90), vhb @1536
//  edge: 288-float staging @0
#define VH_OFF     1536
#define MG9_OFF    1088
#define WARP_STRIDE 1920
#define NWARPS     16
#define SMEM_FLOATS (OFF_WARP + NWARPS * WARP_STRIDE)
#define SMEM_BYTES  (SMEM_FLOATS * 4)

// ================= kernel 1: zero scratch =================
__global__ void k_zero(void)
{
    int i = blockIdx.x * blockDim.x + threadIdx.x;
    if (i == 0) { g_ticket = 0; g_ticket2 = 0; g_edge_done = 0; g_main_done = 0; }
    if (i < MAXN * 3) g_acc[i] = make_float4(0.f, 0.f, 0.f, 0.f);
}

// ================= fused kernel =================
__global__ void __launch_bounds__(512, 1)
k_fused(const float* __restrict__ scalar,
        const float* __restrict__ vector,
        const int*   __restrict__ row,
        const float* __restrict__ frames,
        const float* __restrict__ W_down, const float* __restrict__ W_df,
        const float* __restrict__ W_so,   const float* __restrict__ b_so,
        const float* __restrict__ W_up,   const float* __restrict__ W_g,
        const float* __restrict__ b_g,
        float* __restrict__ out1, float* __restrict__ out2, int N, int E)
{
    extern __shared__ float sm[];
    const int tid  = threadIdx.x;
    const int wid  = tid >> 5;
    const int lane = tid & 31;
    const int lane4 = lane << 2;

    // ---- stage weights ----
    for (int i = tid; i < 153 * 128; i += blockDim.x) {
        int o = i / 153, k = i - o * 153;
        sm[OFF_WSO + k * 132 + o] = W_so[i];
    }
    for (int i = tid; i < 128 * 16; i += blockDim.x) {
        int o = i >> 7, k = i & 127;
        sm[OFF_WG + o * 134 + k] = W_g[i];
    }
    for (int i = tid; i < 256; i += blockDim.x) {
        int o = i >> 4, h = i & 15;
        sm[OFF_WUP + h * 16 + o] = W_up[i];
        int hh = i >> 4, c = i & 15;
        sm[OFF_WDOWN + c * 16 + hh] = W_down[i];
    }
    for (int i = tid; i < 48; i += blockDim.x) {
        int c = i >> 4, k = i & 15;
        sm[OFF_WDF + k * 3 + c] = W_df[i];
    }
    for (int i = tid; i < 128; i += blockDim.x) sm[OFF_BSO + i] = b_so[i];
    for (int i = tid; i < 16;  i += blockDim.x) sm[OFF_BG  + i] = b_g[i];
    __syncthreads();

    float* wb   = sm + OFF_WARP + wid * WARP_STRIDE;
    float* mgT  = wb;
    float* vecb = wb;
    float* vhb  = wb + VH_OFF;
    float* mgT9 = wb + MG9_OFF;

    const int o16 = lane & 15;
    const int h16 = lane >> 4;

    const int NM = (N + NPW - 1) / NPW;
    const int NE = (E + EPT - 1) / EPT;
    const int mm = (NE < NM) ? NE : NM;
    const int totV = N * 48;

    // ================== phase A: edge + main tasks, interleaved ==================
    for (;;) {
        int t = 0;
        if (lane == 0) t = atomicAdd(&g_ticket, 1);
        t = __shfl_sync(0xffffffffu, t, 0);
        if (t >= NE + NM) break;

        bool isEdge; int id;
        if (t < 2 * mm) { isEdge = ((t & 1) == 0); id = t >> 1; }
        else           { int r = t - 2 * mm; isEdge = (NE > NM); id = mm + r; }

        if (isEdge) {
            // ------- edge task: 256 edges -------
            const long tb = (long)id * EPT;
#pragma unroll 1
            for (int rr = 0; rr < 8; rr++) {
                const long e0 = tb + rr * 32;
                if (e0 >= E) break;
                const int cnt = (int)min((long)32, (long)E - e0);
                if (cnt == 32) {
                    const float4* src = (const float4*)(frames + e0 * 9);
#pragma unroll
                    for (int i = 0; i < 2; i++) ((float4*)wb)[lane + 32 * i] = src[lane + 32 * i];
                    if (lane < 8) ((float4*)wb)[64 + lane] = src[64 + lane];
                } else {
                    for (int i = lane; i < cnt * 9; i += 32) wb[i] = frames[e0 * 9 + i];
                }
                int s = (lane < cnt) ? row[e0 + lane] : -1;
                __syncwarp();
                if (s >= 0) {
                    const float* f = &wb[lane * 9];
                    float* dst = (float*)(g_acc + (size_t)s * 3);
                    asm volatile("red.global.add.v4.f32 [%0], {%1,%2,%3,%4};"
                                 :: "l"(dst), "f"(f[0]), "f"(f[1]), "f"(f[2]), "f"(f[3]) : "memory");
                    asm volatile("red.global.add.v4.f32 [%0], {%1,%2,%3,%4};"
                                 :: "l"(dst + 4), "f"(f[4]), "f"(f[5]), "f"(f[6]), "f"(f[7]) : "memory");
                    asm volatile("red.global.add.v4.f32 [%0], {%1,%2,%3,%4};"
                                 :: "l"(dst + 8), "f"(f[8]), "f"(1.0f), "f"(0.0f), "f"(0.0f) : "memory");
                }
                __syncwarp();
            }
            __threadfence();
            if (lane == 0) atomicAdd(&g_edge_done, 1);
        } else {
            // ------- main task: 8 nodes, K=144 GEMM -------
            const int base = id * NPW;
            {
                const int gb = base * 48;
#pragma unroll
                for (int i = 0; i < 12; i++) {
                    int idx = lane + 32 * i;
                    vecb[idx] = (gb + idx < totV) ? vector[gb + idx] : 0.0f;
                }
            }
            __syncwarp();
            // vh + vnorm (full warp)
#pragma unroll
            for (int tt = 0; tt < 4; tt++) {
                const int p = lane + 32 * tt;
                const int j = p >> 4, h = p & 15;
                float vh0 = 0.f, vh1 = 0.f, vh2 = 0.f;
#pragma unroll
                for (int c = 0; c < 16; c++) {
                    float w = sm[OFF_WDOWN + c * 16 + h];
                    vh0 = fmaf(w, vecb[j * 48 + c * 3 + 0], vh0);
                    vh1 = fmaf(w, vecb[j * 48 + c * 3 + 1], vh1);
                    vh2 = fmaf(w, vecb[j * 48 + c * 3 + 2], vh2);
                }
                mgT[(128 + h) * 10 + j] = sqrtf(vh0 * vh0 + vh1 * vh1 + vh2 * vh2 + EPS);
                vhb[j * 48 +      h] = vh0;
                vhb[j * 48 + 16 + h] = vh1;
                vhb[j * 48 + 32 + h] = vh2;
            }
            // vdf -> gmem (lanes < 24)
            if (lane < 24) {
                const int j = lane / 3, c = lane - 3 * j;
                const int n = base + j;
                float d0 = 0.f, d1 = 0.f, d2 = 0.f;
#pragma unroll
                for (int k = 0; k < 16; k++) {
                    float w = sm[OFF_WDF + k * 3 + c];
                    d0 = fmaf(w, vecb[j * 48 + k * 3 + 0], d0);
                    d1 = fmaf(w, vecb[j * 48 + k * 3 + 1], d1);
                    d2 = fmaf(w, vecb[j * 48 + k * 3 + 2], d2);
                }
                if (n < N) {
                    float* vp = g_vdf + (size_t)n * 12 + c * 4;
                    vp[0] = d0; vp[1] = d1; vp[2] = d2;
                }
            }
            __syncwarp();
            // scalar features -> mgT rows 0..127
#pragma unroll
            for (int j = 0; j < NPW; j++) {
                const int n = base + j;
                if (n < N) {
                    const float* sp = scalar + (size_t)n * 128;
#pragma unroll
                    for (int i = 0; i < 4; i++)
                        mgT[(lane + 32 * i) * 10 + j] = sp[lane + 32 * i];
                } else {
#pragma unroll
                    for (int i = 0; i < 4; i++)
                        mgT[(lane + 32 * i) * 10 + j] = 0.0f;
                }
            }
            __syncwarp();

            const float4 bb = *(const float4*)&sm[OFF_BSO + lane4];
            ull a0_0 = pk2(bb.x, bb.x), a0_1 = a0_0, a0_2 = a0_0, a0_3 = a0_0;
            ull a1_0 = pk2(bb.y, bb.y), a1_1 = a1_0, a1_2 = a1_0, a1_3 = a1_0;
            ull a2_0 = pk2(bb.z, bb.z), a2_1 = a2_0, a2_2 = a2_0, a2_3 = a2_0;
            ull a3_0 = pk2(bb.w, bb.w), a3_1 = a3_0, a3_2 = a3_0, a3_3 = a3_0;

#pragma unroll 3
            for (int k = 0; k < 144; k++) {
                const float4 w4 = *(const float4*)&sm[OFF_WSO + k * 132 + lane4];
                const ull w0 = pk2(w4.x, w4.x);
                const ull w1 = pk2(w4.y, w4.y);
                const ull w2 = pk2(w4.z, w4.z);
                const ull w3 = pk2(w4.w, w4.w);
                const ull* mrow = (const ull*)(mgT + k * 10);
                const ull m0 = mrow[0], m1 = mrow[1], m2 = mrow[2], m3 = mrow[3];
                a0_0 = ffma2(w0, m0, a0_0); a0_1 = ffma2(w0, m1, a0_1);
                a0_2 = ffma2(w0, m2, a0_2); a0_3 = ffma2(w0, m3, a0_3);
                a1_0 = ffma2(w1, m0, a1_0); a1_1 = ffma2(w1, m1, a1_1);
                a1_2 = ffma2(w1, m2, a1_2); a1_3 = ffma2(w1, m3, a1_3);
                a2_0 = ffma2(w2, m0, a2_0); a2_1 = ffma2(w2, m1, a2_1);
                a2_2 = ffma2(w2, m2, a2_2); a2_3 = ffma2(w2, m3, a2_3);
                a3_0 = ffma2(w3, m0, a3_0); a3_1 = ffma2(w3, m1, a3_1);
                a3_2 = ffma2(w3, m2, a3_2); a3_3 = ffma2(w3, m3, a3_3);
            }

            // store partial s + vh
            {
                ull A[4][4] = {{a0_0,a0_1,a0_2,a0_3},{a1_0,a1_1,a1_2,a1_3},
                               {a2_0,a2_1,a2_2,a2_3},{a3_0,a3_1,a3_2,a3_3}};
#pragma unroll
                for (int p = 0; p < 4; p++) {
                    float lo[4], hi[4];
#pragma unroll
                    for (int i = 0; i < 4; i++) unpk2(A[i][p], lo[i], hi[i]);
                    int n0 = base + 2 * p, n1 = n0 + 1;
                    if (n0 < N) *(float4*)(g_s + (size_t)n0 * 128 + lane4) =
                        make_float4(lo[0], lo[1], lo[2], lo[3]);
                    if (n1 < N) *(float4*)(g_s + (size_t)n1 * 128 + lane4) =
                        make_float4(hi[0], hi[1], hi[2], hi[3]);
                }
            }
            {
                const int gb = base * 48;
#pragma unroll
                for (int i = 0; i < 12; i++) {
                    int idx = lane + 32 * i;
                    if (gb + idx < totV) g_vh[gb + idx] = vhb[idx];
                }
            }
            __threadfence();
            if (lane == 0) atomicAdd(&g_main_done, 1);
        }
    }

    // ================== wait for all edges + mains ==================
    if (lane == 0) {
        while (ld_acq(&g_edge_done) < NE || ld_acq(&g_main_done) < NM)
            __nanosleep(128);
    }
    __syncwarp();

    // ================== phase B: fix tasks ==================
    for (;;) {
        int t = 0;
        if (lane == 0) t = atomicAdd(&g_ticket2, 1);
        t = __shfl_sync(0xffffffffu, t, 0);
        if (t >= NM) break;
        const int base = t * NPW;

        // stage vh
        {
            const int gb = base * 48;
#pragma unroll
            for (int i = 0; i < 12; i++) {
                int idx = lane + 32 * i;
                vhb[idx] = (gb + idx < totV) ? g_vh[gb + idx] : 0.0f;
            }
        }
        // sh -> mgT9 [q*10 + j]
        if (lane < 24) {
            const int j = lane / 3, c = lane - 3 * j;
            const int n = base + j;
            float d0 = 0.f, d1 = 0.f, d2 = 0.f;
            float4 q0, q1, q2;
            if (n < N) {
                const float* vp = g_vdf + (size_t)n * 12 + c * 4;
                d0 = vp[0]; d1 = vp[1]; d2 = vp[2];
                q0 = g_acc[(size_t)n * 3 + 0];
                q1 = g_acc[(size_t)n * 3 + 1];
                q2 = g_acc[(size_t)n * 3 + 2];
            } else { q0 = q1 = q2 = make_float4(0, 0, 0, 1); }
            float inv = __fdividef(1.0f, fmaxf(q2.y, 1.0f));
            mgT9[(c * 3 + 0) * 10 + j] = (q0.x * d0 + q0.y * d1 + q0.z * d2) * inv;
            mgT9[(c * 3 + 1) * 10 + j] = (q0.w * d0 + q1.x * d1 + q1.y * d2) * inv;
            mgT9[(c * 3 + 2) * 10 + j] = (q1.z * d0 + q1.w * d1 + q2.x * d2) * inv;
        }
        __syncwarp();

        // load partial s, pack into accumulators
        float4 sv[NPW];
#pragma unroll
        for (int j = 0; j < NPW; j++) {
            const int n = base + j;
            sv[j] = (n < N) ? *(const float4*)(g_s + (size_t)n * 128 + lane4)
                            : make_float4(0, 0, 0, 0);
        }
        ull a0_0 = pk2(sv[0].x, sv[1].x), a0_1 = pk2(sv[2].x, sv[3].x),
            a0_2 = pk2(sv[4].x, sv[5].x), a0_3 = pk2(sv[6].x, sv[7].x);
        ull a1_0 = pk2(sv[0].y, sv[1].y), a1_1 = pk2(sv[2].y, sv[3].y),
            a1_2 = pk2(sv[4].y, sv[5].y), a1_3 = pk2(sv[6].y, sv[7].y);
        ull a2_0 = pk2(sv[0].z, sv[1].z), a2_1 = pk2(sv[2].z, sv[3].z),
            a2_2 = pk2(sv[4].z, sv[5].z), a2_3 = pk2(sv[6].z, sv[7].z);
        ull a3_0 = pk2(sv[0].w, sv[1].w), a3_1 = pk2(sv[2].w, sv[3].w),
            a3_2 = pk2(sv[4].w, sv[5].w), a3_3 = pk2(sv[6].w, sv[7].w);

#pragma unroll
        for (int q = 0; q < 9; q++) {
            const float4 w4 = *(const float4*)&sm[OFF_WSO + (144 + q) * 132 + lane4];
            const ull w0 = pk2(w4.x, w4.x);
            const ull w1 = pk2(w4.y, w4.y);
            const ull w2 = pk2(w4.z, w4.z);
            const ull w3 = pk2(w4.w, w4.w);
            const ull* mrow = (const ull*)(mgT9 + q * 10);
            const ull m0 = mrow[0], m1 = mrow[1], m2 = mrow[2], m3 = mrow[3];
            a0_0 = ffma2(w0, m0, a0_0); a0_1 = ffma2(w0, m1, a0_1);
            a0_2 = ffma2(w0, m2, a0_2); a0_3 = ffma2(w0, m3, a0_3);
            a1_0 = ffma2(w1, m0, a1_0); a1_1 = ffma2(w1, m1, a1_1);
            a1_2 = ffma2(w1, m2, a1_2); a1_3 = ffma2(w1, m3, a1_3);
            a2_0 = ffma2(w2, m0, a2_0); a2_1 = ffma2(w2, m1, a2_1);
            a2_2 = ffma2(w2, m2, a2_2); a2_3 = ffma2(w2, m3, a2_3);
            a3_0 = ffma2(w3, m0, a3_0); a3_1 = ffma2(w3, m1, a3_1);
            a3_2 = ffma2(w3, m2, a3_2); a3_3 = ffma2(w3, m3, a3_3);
        }
        __syncwarp();

        // silu + out1 + msil [j*132 + k]
        float sil[4][NPW];
        {
            ull A[4][4] = {{a0_0,a0_1,a0_2,a0_3},{a1_0,a1_1,a1_2,a1_3},
                           {a2_0,a2_1,a2_2,a2_3},{a3_0,a3_1,a3_2,a3_3}};
#pragma unroll
            for (int i = 0; i < 4; i++)
#pragma unroll
                for (int p = 0; p < 4; p++) {
                    float lo, hi; unpk2(A[i][p], lo, hi);
                    sil[i][2*p]   = __fdividef(lo, 1.0f + __expf(-lo));
                    sil[i][2*p+1] = __fdividef(hi, 1.0f + __expf(-hi));
                }
        }
        float* msil = wb;
#pragma unroll
        for (int j = 0; j < NPW; j++) {
            float4 o4 = make_float4(sil[0][j], sil[1][j], sil[2][j], sil[3][j]);
            *(float4*)&msil[j * 132 + lane4] = o4;
            if (base + j < N)
                *(float4*)(out1 + (size_t)(base + j) * 128 + lane4) = o4;
        }
        __syncwarp();

        // gate GEMM
        const float bgv = sm[OFF_BG + o16];
        ull g01[4];
#pragma unroll
        for (int p = 0; p < 4; p++) g01[p] = 0ull;
#pragma unroll 8
        for (int kp = 0; kp < 64; kp++) {
            const int k = kp * 2;
            const ull wgp = *(const ull*)&sm[OFF_WG + o16 * 134 + k];
#pragma unroll
            for (int p = 0; p < 4; p++) {
                const int j = 4 * h16 + p;
                const ull mp = *(const ull*)&msil[j * 132 + k];
                g01[p] = ffma2(wgp, mp, g01[p]);
            }
        }

        // vrep
#pragma unroll
        for (int p = 0; p < 4; p++) {
            const int j = 4 * h16 + p;
            const int n = base + j;
            float lo, hi; unpk2(g01[p], lo, hi);
            const float gvv = lo + hi + bgv;
            const float sg = __fdividef(1.0f, 1.0f + __expf(-gvv));
            const float* vh = vhb + j * 48;
            float r0 = 0.f, r1 = 0.f, r2 = 0.f;
#pragma unroll
            for (int hh = 0; hh < 16; hh++) {
                const float w = sm[OFF_WUP + hh * 16 + o16];
                r0 = fmaf(w, vh[hh],      r0);
                r1 = fmaf(w, vh[16 + hh], r1);
                r2 = fmaf(w, vh[32 + hh], r2);
            }
            if (n < N) {
                float* od = out2 + (size_t)n * 48 + o16 * 3;
                od[0] = r0 * sg; od[1] = r1 * sg; od[2] = r2 * sg;
            }
        }
        __syncwarp();
    }
}

// ================= launch =================
extern "C" void kernel_launch(void* const* d_in, const int* in_sizes, int n_in,
                              void* d_out, int out_size)
{
    const float* scalar  = (const float*)d_in[0];
    const float* vector  = (const float*)d_in[1];
    const int*   eidx    = (const int*)  d_in[2];
    const float* frames  = (const float*)d_in[3];
    const float* W_down  = (const float*)d_in[4];
    const float* W_df    = (const float*)d_in[5];
    const float* W_so    = (const float*)d_in[6];
    const float* b_so    = (const float*)d_in[7];
    const float* W_up    = (const float*)d_in[8];
    const float* W_g     = (const float*)d_in[9];
    const float* b_g     = (const float*)d_in[10];

    const int N = in_sizes[0] / 128;
    const int E = in_sizes[2] / 2;
    const int* row = eidx;

    float* out1 = (float*)d_out;
    float* out2 = out1 + (size_t)N * 128;

    cudaFuncSetAttribute(k_fused, cudaFuncAttributeMaxDynamicSharedMemorySize,
                         SMEM_BYTES);

    k_zero<<<(MAXN * 3 + 255) / 256, 256>>>();
    k_fused<<<148, 512, SMEM_BYTES>>>(scalar, vector, row, frames,
                                      W_down, W_df, W_so, b_so, W_up, W_g, b_g,
                                      out1, out2, N, E);
}

// round 8
// speedup vs baseline: 1.0817x; 1.0817x over previous
#include <cuda_runtime.h>
#include <math.h>

#define MAXN 50000
#define EPS  1e-8f

typedef unsigned long long ull;

// ---- scratch ----
__device__ float4 g_acc[MAXN * 3];   // [0..8]=frame sum, [9]=count, pad
__device__ int    g_ticket;

// ---- packed f32x2 helpers ----
__device__ __forceinline__ ull pk2(float lo, float hi) {
    ull r; asm("mov.b64 %0, {%1,%2};" : "=l"(r) : "f"(lo), "f"(hi)); return r;
}
__device__ __forceinline__ void unpk2(ull v, float& lo, float& hi) {
    asm("mov.b64 {%0,%1}, %2;" : "=f"(lo), "=f"(hi) : "l"(v));
}
__device__ __forceinline__ ull ffma2(ull a, ull b, ull c) {
    ull d; asm("fma.rn.f32x2 %0, %1, %2, %3;" : "=l"(d) : "l"(a), "l"(b), "l"(c));
    return d;
}

// ---- shared layout (floats) ----
#define OFF_WSO    0                        // [k*132 + o], k<153
#define SZ_WSO     20200
#define OFF_WG     (OFF_WSO + SZ_WSO)       // [o*136 + k]  (16B-aligned rows)
#define SZ_WG      2176
#define OFF_WUP    (OFF_WG + SZ_WG)         // [h*16 + o]
#define SZ_WUP     256
#define OFF_WDOWN  (OFF_WUP + SZ_WUP)       // [c*16 + h]
#define SZ_WDOWN   256
#define OFF_WDF    (OFF_WDOWN + SZ_WDOWN)   // [k*3 + c]
#define SZ_WDF     48
#define OFF_BSO    (OFF_WDF + SZ_WDF)
#define SZ_BSO     128
#define OFF_BG     (OFF_BSO + SZ_BSO)
#define SZ_BG      16
#define OFF_WARP   (OFF_BG + SZ_BG)         // 23080: multiple of 4 -> 16B aligned
// per-warp: mgT[k*12 + j] k<153 (1836; rows 0..31 transiently = vec buffer;
//           reused as msil[j*136+k] (1088) in epilogue), vhb @1836 (384)
#define MGT_SZ     1836
#define VH_OFF     MGT_SZ
#define WARP_STRIDE 2220
#define NWARPS     15
#define NPW        8
#define SMEM_FLOATS (OFF_WARP + NWARPS * WARP_STRIDE)
#define SMEM_BYTES  (SMEM_FLOATS * 4)

// ================= kernel 1: zero scratch =================
__global__ void k_zero(void)
{
    int i = blockIdx.x * blockDim.x + threadIdx.x;
    if (i == 0) g_ticket = 0;
    if (i < MAXN * 3) g_acc[i] = make_float4(0.f, 0.f, 0.f, 0.f);
}

// ================= kernel 2: edge scatter (vector RED) =====
__global__ void __launch_bounds__(256)
k_edges(const int* __restrict__ row, const float* __restrict__ frames, int E)
{
    __shared__ float buf[8][288];
    const int w = threadIdx.x >> 5, lane = threadIdx.x & 31;
    const long e0 = ((long)blockIdx.x * 8 + w) * 32;
    if (e0 >= E) return;
    const int cnt = (int)min((long)32, (long)E - e0);
    const float* src = frames + e0 * 9;
    for (int i = lane; i < cnt * 9; i += 32) buf[w][i] = src[i];
    int s = (lane < cnt) ? row[e0 + lane] : -1;
    __syncwarp();
    if (s >= 0) {
        const float* f = &buf[w][lane * 9];
        float* dst = (float*)(g_acc + (size_t)s * 3);
        asm volatile("red.global.add.v4.f32 [%0], {%1,%2,%3,%4};"
                     :: "l"(dst), "f"(f[0]), "f"(f[1]), "f"(f[2]), "f"(f[3]) : "memory");
        asm volatile("red.global.add.v4.f32 [%0], {%1,%2,%3,%4};"
                     :: "l"(dst + 4), "f"(f[4]), "f"(f[5]), "f"(f[6]), "f"(f[7]) : "memory");
        asm volatile("red.global.add.v4.f32 [%0], {%1,%2,%3,%4};"
                     :: "l"(dst + 8), "f"(f[8]), "f"(1.0f), "f"(0.0f), "f"(0.0f) : "memory");
    }
}

// ================= kernel 3: fused node kernel =============
__global__ void __launch_bounds__(480, 1)
k_nodes(const float* __restrict__ scalar,
        const float* __restrict__ vector,
        const float* __restrict__ W_down, const float* __restrict__ W_df,
        const float* __restrict__ W_so,   const float* __restrict__ b_so,
        const float* __restrict__ W_up,   const float* __restrict__ W_g,
        const float* __restrict__ b_g,
        float* __restrict__ out1, float* __restrict__ out2, int N)
{
    extern __shared__ float sm[];
    const int tid  = threadIdx.x;
    const int wid  = tid >> 5;
    const int lane = tid & 31;
    const int lane4 = lane << 2;

    // ---- stage weights ----
    for (int i = tid; i < 153 * 128; i += blockDim.x) {
        int o = i / 153, k = i - o * 153;
        sm[OFF_WSO + k * 132 + o] = W_so[i];
    }
    for (int i = tid; i < 128 * 16; i += blockDim.x) {
        int o = i >> 7, k = i & 127;
        sm[OFF_WG + o * 136 + k] = W_g[i];
    }
    for (int i = tid; i < 256; i += blockDim.x) {
        int o = i >> 4, h = i & 15;         // W_up[o][h] -> [h*16+o]
        sm[OFF_WUP + h * 16 + o] = W_up[i];
        int hh = i >> 4, c = i & 15;        // W_down[h][c] -> [c*16+h]
        sm[OFF_WDOWN + c * 16 + hh] = W_down[i];
    }
    for (int i = tid; i < 48; i += blockDim.x) {
        int c = i >> 4, k = i & 15;         // W_df (3,16)
        sm[OFF_WDF + k * 3 + c] = W_df[i];
    }
    for (int i = tid; i < 128; i += blockDim.x) sm[OFF_BSO + i] = b_so[i];
    for (int i = tid; i < 16;  i += blockDim.x) sm[OFF_BG  + i] = b_g[i];
    __syncthreads();

    float* wb   = sm + OFF_WARP + wid * WARP_STRIDE;
    float* mgT  = wb;                 // [k*12 + j]
    float* vecb = wb;                 // aliases mgT rows 0..31 (transient)
    float* vhb  = wb + VH_OFF;        // [j*48 + d*16 + h]

    const int o16 = lane & 15;
    const int h16 = lane >> 4;

    // persistent per-lane weight columns
    float wu[16], wd[16];
#pragma unroll
    for (int hh = 0; hh < 16; hh++) {
        wu[hh] = sm[OFF_WUP   + hh * 16 + o16];
        wd[hh] = sm[OFF_WDOWN + hh * 16 + o16];   // wd[c] for h = o16
    }

    const float4 bb  = *(const float4*)&sm[OFF_BSO + lane4];
    const float  bgv = sm[OFF_BG + o16];

    const int nGroups = (N + NPW - 1) / NPW;
    const int totV = N * 48;

    for (;;) {
        int grp = 0;
        if (lane == 0) grp = atomicAdd(&g_ticket, 1);
        grp = __shfl_sync(0xffffffffu, grp, 0);
        if (grp >= nGroups) break;
        const int base = grp * NPW;

        // ---------- prep phase 1: load 8 node vectors into vecb ----------
        {
            const int gb = base * 48;
#pragma unroll
            for (int i = 0; i < 12; i++) {
                int idx = lane + 32 * i;
                vecb[idx] = (gb + idx < totV) ? vector[gb + idx] : 0.0f;
            }
        }
        __syncwarp();

        // ---------- prep phase 2: vh (full warp, h = o16, j = h16+2t) ----------
#pragma unroll
        for (int t = 0; t < 4; t++) {
            const int j = h16 + 2 * t;
            const int h = o16;
            float vh0 = 0.f, vh1 = 0.f, vh2 = 0.f;
#pragma unroll
            for (int c = 0; c < 16; c++) {
                const float w = wd[c];
                vh0 = fmaf(w, vecb[j * 48 + c * 3 + 0], vh0);
                vh1 = fmaf(w, vecb[j * 48 + c * 3 + 1], vh1);
                vh2 = fmaf(w, vecb[j * 48 + c * 3 + 2], vh2);
            }
            mgT[(128 + h) * 12 + j] = sqrtf(vh0 * vh0 + vh1 * vh1 + vh2 * vh2 + EPS);
            vhb[j * 48 +      h] = vh0;
            vhb[j * 48 + 16 + h] = vh1;
            vhb[j * 48 + 32 + h] = vh2;
        }
        // sh (lanes < 24)
        if (lane < 24) {
            const int j = lane / 3, c = lane - 3 * j;
            const int n = base + j;
            float d0 = 0.f, d1 = 0.f, d2 = 0.f;
#pragma unroll
            for (int k = 0; k < 16; k++) {
                float w = sm[OFF_WDF + k * 3 + c];
                d0 = fmaf(w, vecb[j * 48 + k * 3 + 0], d0);
                d1 = fmaf(w, vecb[j * 48 + k * 3 + 1], d1);
                d2 = fmaf(w, vecb[j * 48 + k * 3 + 2], d2);
            }
            float4 q0, q1, q2;
            if (n < N) {
                q0 = g_acc[(size_t)n * 3 + 0];
                q1 = g_acc[(size_t)n * 3 + 1];
                q2 = g_acc[(size_t)n * 3 + 2];
            } else { q0 = q1 = q2 = make_float4(0, 0, 0, 1); }
            float inv = __fdividef(1.0f, fmaxf(q2.y, 1.0f));
            mgT[(144 + c * 3 + 0) * 12 + j] = (q0.x * d0 + q0.y * d1 + q0.z * d2) * inv;
            mgT[(144 + c * 3 + 1) * 12 + j] = (q0.w * d0 + q1.x * d1 + q1.y * d2) * inv;
            mgT[(144 + c * 3 + 2) * 12 + j] = (q1.z * d0 + q1.w * d1 + q2.x * d2) * inv;
        }
        __syncwarp();

        // ---------- prep phase 3: scalar features -> mgT rows 0..127 ----------
#pragma unroll
        for (int j = 0; j < NPW; j++) {
            const int n = base + j;
            if (n < N) {
                const float* sp = scalar + (size_t)n * 128;
#pragma unroll
                for (int i = 0; i < 4; i++)
                    mgT[(lane + 32 * i) * 12 + j] = sp[lane + 32 * i];
            } else {
#pragma unroll
                for (int i = 0; i < 4; i++)
                    mgT[(lane + 32 * i) * 12 + j] = 0.0f;
            }
        }
        __syncwarp();

        // ---------- main GEMM: FFMA2, 8 nodes x 4 outputs/lane, K=153 ----------
        ull a0_0 = pk2(bb.x, bb.x), a0_1 = a0_0, a0_2 = a0_0, a0_3 = a0_0;
        ull a1_0 = pk2(bb.y, bb.y), a1_1 = a1_0, a1_2 = a1_0, a1_3 = a1_0;
        ull a2_0 = pk2(bb.z, bb.z), a2_1 = a2_0, a2_2 = a2_0, a2_3 = a2_0;
        ull a3_0 = pk2(bb.w, bb.w), a3_1 = a3_0, a3_2 = a3_0, a3_3 = a3_0;

#pragma unroll 3
        for (int k = 0; k < 153; k++) {
            const float4 w4 = *(const float4*)&sm[OFF_WSO + k * 132 + lane4];
            const ull w0 = pk2(w4.x, w4.x);
            const ull w1 = pk2(w4.y, w4.y);
            const ull w2 = pk2(w4.z, w4.z);
            const ull w3 = pk2(w4.w, w4.w);
            const longlong2 ma = *(const longlong2*)(mgT + k * 12);
            const longlong2 mb = *(const longlong2*)(mgT + k * 12 + 4);
            const ull m0 = (ull)ma.x, m1 = (ull)ma.y;
            const ull m2 = (ull)mb.x, m3 = (ull)mb.y;
            a0_0 = ffma2(w0, m0, a0_0); a0_1 = ffma2(w0, m1, a0_1);
            a0_2 = ffma2(w0, m2, a0_2); a0_3 = ffma2(w0, m3, a0_3);
            a1_0 = ffma2(w1, m0, a1_0); a1_1 = ffma2(w1, m1, a1_1);
            a1_2 = ffma2(w1, m2, a1_2); a1_3 = ffma2(w1, m3, a1_3);
            a2_0 = ffma2(w2, m0, a2_0); a2_1 = ffma2(w2, m1, a2_1);
            a2_2 = ffma2(w2, m2, a2_2); a2_3 = ffma2(w2, m3, a2_3);
            a3_0 = ffma2(w3, m0, a3_0); a3_1 = ffma2(w3, m1, a3_1);
            a3_2 = ffma2(w3, m2, a3_2); a3_3 = ffma2(w3, m3, a3_3);
        }
        __syncwarp();

        // ---------- silu + out1 + msil [j*136 + k] ----------
        float sil[4][NPW];
        {
            ull A[4][4] = {{a0_0,a0_1,a0_2,a0_3},{a1_0,a1_1,a1_2,a1_3},
                           {a2_0,a2_1,a2_2,a2_3},{a3_0,a3_1,a3_2,a3_3}};
#pragma unroll
            for (int i = 0; i < 4; i++)
#pragma unroll
                for (int p = 0; p < 4; p++) {
                    float lo, hi; unpk2(A[i][p], lo, hi);
                    sil[i][2*p]   = __fdividef(lo, 1.0f + __expf(-lo));
                    sil[i][2*p+1] = __fdividef(hi, 1.0f + __expf(-hi));
                }
        }
        float* msil = wb;   // overwrites mgT
#pragma unroll
        for (int j = 0; j < NPW; j++) {
            float4 o4 = make_float4(sil[0][j], sil[1][j], sil[2][j], sil[3][j]);
            *(float4*)&msil[j * 136 + lane4] = o4;
            if (base + j < N)
                *(float4*)(out1 + (size_t)(base + j) * 128 + lane4) = o4;
        }
        __syncwarp();

        // ---------- gate GEMM: 4-k steps, LDS.128 both sides ----------
        ull gA[4], gB[4];
#pragma unroll
        for (int p = 0; p < 4; p++) { gA[p] = 0ull; gB[p] = 0ull; }
#pragma unroll 4
        for (int kq = 0; kq < 128; kq += 4) {
            const longlong2 wg = *(const longlong2*)&sm[OFF_WG + o16 * 136 + kq];
            const ull wg0 = (ull)wg.x, wg1 = (ull)wg.y;
#pragma unroll
            for (int p = 0; p < 4; p++) {
                const int j = 4 * h16 + p;
                const longlong2 mp = *(const longlong2*)&msil[j * 136 + kq];
                gA[p] = ffma2(wg0, (ull)mp.x, gA[p]);
                gB[p] = ffma2(wg1, (ull)mp.y, gB[p]);
            }
        }

        // ---------- vrep ----------
#pragma unroll
        for (int p = 0; p < 4; p++) {
            const int j = 4 * h16 + p;
            const int n = base + j;
            float la, ha, lb, hb2;
            unpk2(gA[p], la, ha); unpk2(gB[p], lb, hb2);
            const float gvv = ((la + lb) + (ha + hb2)) + bgv;
            const float sg = __fdividef(1.0f, 1.0f + __expf(-gvv));
            const float* vh = vhb + j * 48;
            float r0 = 0.f, r1 = 0.f, r2 = 0.f;
#pragma unroll
            for (int hh = 0; hh < 16; hh++) {
                r0 = fmaf(wu[hh], vh[hh],      r0);
                r1 = fmaf(wu[hh], vh[16 + hh], r1);
                r2 = fmaf(wu[hh], vh[32 + hh], r2);
            }
            if (n < N) {
                float* od = out2 + (size_t)n * 48 + o16 * 3;
                od[0] = r0 * sg; od[1] = r1 * sg; od[2] = r2 * sg;
            }
        }
        __syncwarp();
    }
}

// ================= launch =================
extern "C" void kernel_launch(void* const* d_in, const int* in_sizes, int n_in,
                              void* d_out, int out_size)
{
    const float* scalar  = (const float*)d_in[0];
    const float* vector  = (const float*)d_in[1];
    const int*   eidx    = (const int*)  d_in[2];
    const float* frames  = (const float*)d_in[3];
    const float* W_down  = (const float*)d_in[4];
    const float* W_df    = (const float*)d_in[5];
    const float* W_so    = (const float*)d_in[6];
    const float* b_so    = (const float*)d_in[7];
    const float* W_up    = (const float*)d_in[8];
    const float* W_g     = (const float*)d_in[9];
    const float* b_g     = (const float*)d_in[10];

    const int N = in_sizes[0] / 128;
    const int E = in_sizes[2] / 2;
    const int* row = eidx;

    float* out1 = (float*)d_out;
    float* out2 = out1 + (size_t)N * 128;

    cudaFuncSetAttribute(k_nodes, cudaFuncAttributeMaxDynamicSharedMemorySize,
                         SMEM_BYTES);

    k_zero<<<(MAXN * 3 + 255) / 256, 256>>>();
    k_edges<<<(E + 255) / 256, 256>>>(row, frames, E);
    k_nodes<<<148, 480, SMEM_BYTES>>>(scalar, vector, W_down, W_df, W_so, b_so,
                                      W_up, W_g, b_g, out1, out2, N);
}